// round 13
// baseline (speedup 1.0000x reference)
#include <cuda_runtime.h>
#include <cuda_fp16.h>
#include <cstdint>

#define NN 50000
#define NE 800000
#define CAP 96         // per-node bucket capacity (Poisson(16) max deg ~45)
#define TILES 391      // ceil(50000/128)

// ---------------- scratch (device globals: no allocs allowed) ----------------
__device__ int    g_cnt[NN];
__device__ float  g_rinv[NN];
__device__ int    g_bkt[NN * CAP];
__device__ float  g_sumw[NN];
__device__ __half g_h2s[NN * 128];     // fp16 copy of h, PRE-SCALED by rinv[row]
__device__ __half g_agg[NN * 128];     // aggregated features, fp16 row-major
__device__ __half g_Bh[128 * 128];     // W fp16 row-major: Bh[n][k] = W[n][k]

__device__ __forceinline__ unsigned h2u(__half2 v) {
    return *reinterpret_cast<unsigned*>(&v);
}
__device__ __forceinline__ __half2 u2h(unsigned v) {
    return *reinterpret_cast<__half2*>(&v);
}
__device__ __forceinline__ uint32_t smem_u32(const void* p) {
    uint32_t a;
    asm("{ .reg .u64 t; cvta.to.shared.u64 t, %1; cvt.u32.u64 %0, t; }" : "=r"(a) : "l"(p));
    return a;
}

// ---------------- init: zero counters + W -> fp16 ----------------
__global__ void k_init(const float* __restrict__ W) {
    int i = blockIdx.x * 256 + threadIdx.x;      // 196*256 = 50176
    if (i < NN) g_cnt[i] = 0;
    if (i < 128 * 128) g_Bh[i] = __float2half(W[i]);
}

// ---------------- fill buckets (counts degrees as a side effect) ----------------
__global__ void k_fill(const int* __restrict__ ed) {
    int e = blockIdx.x * 256 + threadIdx.x;
    if (e < NE) {
        int s = ed[e];
        int d = ed[NE + e];
        int p = atomicAdd(&g_cnt[d], 1);
        if (p < CAP) g_bkt[d * CAP + p] = s;
    }
}

// ---------------- convert (fused rinv): h2s[row][c] = fp16(h[row][c]*rinv[row]) ----------------
__global__ void k_conv(const float* __restrict__ h) {
    int i = blockIdx.x * 256 + threadIdx.x;      // 3125*256 = 800000
    int node = i >> 4;                           // 16 threads per 128-col row
    float rv = rsqrtf((float)(g_cnt[node] + 1));
    if ((i & 15) == 0) g_rinv[node] = rv;
    size_t base = (size_t)i * 8;
    float4 f0 = *(const float4*)(h + base);
    float4 f1 = *(const float4*)(h + base + 4);
    uint4 pack;
    pack.x = h2u(__floats2half2_rn(rv * f0.x, rv * f0.y));
    pack.y = h2u(__floats2half2_rn(rv * f0.z, rv * f0.w));
    pack.z = h2u(__floats2half2_rn(rv * f1.x, rv * f1.y));
    pack.w = h2u(__floats2half2_rn(rv * f1.z, rv * f1.w));
    *(uint4*)(g_h2s + base) = pack;
}

// ---------------- aggregation: one warp per dst node ----------------
// Lane owns cols {4l..4l+3} via one LDG.64 per row; fp16 HADD2 accumulation.
// agg[d] = rinv[d] * ( h2s[d] + sum_s h2s[s] );  sumw[d] = rinv[d]*(sum_s rinv[s] + rinv[d])
__global__ void k_gather() {
    int tid = threadIdx.x;
    int w = tid >> 5, lane = tid & 31;
    int node = blockIdx.x * 8 + w;           // 6250*8 = 50000 exactly

    uint2 self = ((const uint2*)(g_h2s + (size_t)node * 128))[lane];
    __half2 accA = u2h(self.x);              // cols 4l, 4l+1
    __half2 accB = u2h(self.y);              // cols 4l+2, 4l+3
    float sr = 0.f;

    int n = g_cnt[node];
    if (n > CAP) n = CAP;
    const int4* bk4 = (const int4*)(g_bkt + node * CAP);
    const int*  bk  = g_bkt + node * CAP;
    int nq = n >> 2;                         // full groups of 4

    if (nq > 0) {
        int4 cur = bk4[0];
        for (int q = 0; q < nq; q++) {
            int qn = q + 1 < (CAP / 4) ? q + 1 : (CAP / 4) - 1;
            int4 nxt = bk4[qn];              // prefetch next indices
            float r0 = g_rinv[cur.x], r1 = g_rinv[cur.y];
            float r2 = g_rinv[cur.z], r3 = g_rinv[cur.w];
            uint2 v0 = ((const uint2*)(g_h2s + (size_t)cur.x * 128))[lane];
            uint2 v1 = ((const uint2*)(g_h2s + (size_t)cur.y * 128))[lane];
            uint2 v2 = ((const uint2*)(g_h2s + (size_t)cur.z * 128))[lane];
            uint2 v3 = ((const uint2*)(g_h2s + (size_t)cur.w * 128))[lane];
            sr += (r0 + r1) + (r2 + r3);
            accA = __hadd2(accA, u2h(v0.x)); accB = __hadd2(accB, u2h(v0.y));
            accA = __hadd2(accA, u2h(v1.x)); accB = __hadd2(accB, u2h(v1.y));
            accA = __hadd2(accA, u2h(v2.x)); accB = __hadd2(accB, u2h(v2.y));
            accA = __hadd2(accA, u2h(v3.x)); accB = __hadd2(accB, u2h(v3.y));
            cur = nxt;
        }
    }
    for (int j = nq * 4; j < n; j++) {
        int s = bk[j];
        uint2 v = ((const uint2*)(g_h2s + (size_t)s * 128))[lane];
        sr += g_rinv[s];
        accA = __hadd2(accA, u2h(v.x));
        accB = __hadd2(accB, u2h(v.y));
    }

    float rd = g_rinv[node];
    __half2 rdh = __float2half2_rn(rd);
    uint2 o;
    o.x = h2u(__hmul2(accA, rdh));
    o.y = h2u(__hmul2(accB, rdh));
    *(uint2*)(g_agg + (size_t)node * 128 + lane * 4) = o;
    if (lane == 0) g_sumw[node] = rd * (sr + rd);
}

// ---------------- HMMA GEMM: out[n,c] = agg[n,:] . W[c,:] + sumw[n]*b[c] ----------------
// Padded smem stride 136 halfs (272 B): ldmatrix rows land on distinct 16B banks.
#define ASTRIDE 136
#define SM_BYTES (2 * 128 * ASTRIDE * 2)   // A + B staging, 69632 B

__global__ void __launch_bounds__(256, 1)
k_mm(const float* __restrict__ bvec, float* __restrict__ out) {
    extern __shared__ __half smem[];
    __half* sA = smem;                       // [128][ASTRIDE]
    __half* sB = smem + 128 * ASTRIDE;       // [128][ASTRIDE]  (n x k)
    int tid = threadIdx.x, wrp = tid >> 5, lane = tid & 31;
    int t = blockIdx.x;

    // stage A (clamp OOB rows) and B; 16B chunks, conflict-free
    for (int i = tid; i < 2048; i += 256) {
        int r = i >> 4, cp = i & 15;
        int node = t * 128 + r;
        if (node >= NN) node = NN - 1;
        *(uint4*)(sA + r * ASTRIDE + cp * 8) =
            *(const uint4*)(g_agg + (size_t)node * 128 + cp * 8);
        *(uint4*)(sB + r * ASTRIDE + cp * 8) =
            *(const uint4*)(g_Bh + (size_t)r * 128 + cp * 8);
    }
    __syncthreads();

    int mbase = (wrp & 3) * 32;     // 4 warps over M
    int nbase = (wrp >> 2) * 64;    // 2 warps over N

    float c[2][8][4];
    #pragma unroll
    for (int mt = 0; mt < 2; mt++)
        #pragma unroll
        for (int nt = 0; nt < 8; nt++)
            #pragma unroll
            for (int q = 0; q < 4; q++) c[mt][nt][q] = 0.f;

    uint32_t aAddrBase = smem_u32(sA);
    uint32_t bAddrBase = smem_u32(sB);
    int aRow = lane & 15;
    int aK8  = (lane >> 4) << 3;
    int bRowSel = (lane & 7) + ((lane >> 4) << 3);
    int bK8  = ((lane >> 3) & 1) << 3;

    #pragma unroll
    for (int k = 0; k < 8; k++) {
        int kbase = k * 16;
        uint32_t a[2][4];
        #pragma unroll
        for (int mt = 0; mt < 2; mt++) {
            uint32_t addr = aAddrBase +
                ((mbase + mt * 16 + aRow) * ASTRIDE + kbase + aK8) * 2;
            asm volatile("ldmatrix.sync.aligned.m8n8.x4.shared.b16 {%0,%1,%2,%3}, [%4];"
                         : "=r"(a[mt][0]), "=r"(a[mt][1]), "=r"(a[mt][2]), "=r"(a[mt][3])
                         : "r"(addr));
        }
        uint32_t bf[8][2];
        #pragma unroll
        for (int p = 0; p < 4; p++) {
            uint32_t addr = bAddrBase +
                ((nbase + p * 16 + bRowSel) * ASTRIDE + kbase + bK8) * 2;
            asm volatile("ldmatrix.sync.aligned.m8n8.x4.shared.b16 {%0,%1,%2,%3}, [%4];"
                         : "=r"(bf[2 * p][0]), "=r"(bf[2 * p][1]),
                           "=r"(bf[2 * p + 1][0]), "=r"(bf[2 * p + 1][1])
                         : "r"(addr));
        }
        #pragma unroll
        for (int mt = 0; mt < 2; mt++)
            #pragma unroll
            for (int nt = 0; nt < 8; nt++)
                asm volatile(
                    "mma.sync.aligned.m16n8k16.row.col.f32.f16.f16.f32 "
                    "{%0,%1,%2,%3}, {%4,%5,%6,%7}, {%8,%9}, {%0,%1,%2,%3};"
                    : "+f"(c[mt][nt][0]), "+f"(c[mt][nt][1]),
                      "+f"(c[mt][nt][2]), "+f"(c[mt][nt][3])
                    : "r"(a[mt][0]), "r"(a[mt][1]), "r"(a[mt][2]), "r"(a[mt][3]),
                      "r"(bf[nt][0]), "r"(bf[nt][1]));
    }

    // epilogue: direct STG with sumw*bias
    #pragma unroll
    for (int mt = 0; mt < 2; mt++) {
        int r0 = mbase + mt * 16 + (lane >> 2);
        int node0 = t * 128 + r0;
        int node1 = node0 + 8;
        float s0 = (node0 < NN) ? g_sumw[node0] : 0.f;
        float s1 = (node1 < NN) ? g_sumw[node1] : 0.f;
        #pragma unroll
        for (int nt = 0; nt < 8; nt++) {
            int col = nbase + nt * 8 + (lane & 3) * 2;
            float2 bb = *(const float2*)(bvec + col);
            if (node0 < NN) {
                float2 v = { c[mt][nt][0] + s0 * bb.x, c[mt][nt][1] + s0 * bb.y };
                *(float2*)(out + (size_t)node0 * 128 + col) = v;
            }
            if (node1 < NN) {
                float2 v = { c[mt][nt][2] + s1 * bb.x, c[mt][nt][3] + s1 * bb.y };
                *(float2*)(out + (size_t)node1 * 128 + col) = v;
            }
        }
    }
}

// ---------------- launch ----------------
extern "C" void kernel_launch(void* const* d_in, const int* in_sizes, int n_in,
                              void* d_out, int out_size) {
    const float* h = nullptr;
    const float* W = nullptr;
    const float* b = nullptr;
    const int*   ed = nullptr;
    for (int i = 0; i < n_in; i++) {
        switch (in_sizes[i]) {
            case NN * 128:  h  = (const float*)d_in[i]; break;      // 6400000
            case 128 * 128: W  = (const float*)d_in[i]; break;      // 16384
            case 128:       b  = (const float*)d_in[i]; break;      // 128
            case 2 * NE:    ed = (const int*)d_in[i]; break;        // 1600000 int32
        }
    }
    float* out = (float*)d_out;

    cudaFuncSetAttribute(k_mm, cudaFuncAttributeMaxDynamicSharedMemorySize, SM_BYTES);

    k_init   <<<196, 256>>>(W);
    k_fill   <<<3125, 256>>>(ed);
    k_conv   <<<3125, 256>>>(h);
    k_gather <<<6250, 256>>>();
    k_mm     <<<TILES, 256, SM_BYTES>>>(b, out);
}

// round 14
// speedup vs baseline: 1.0535x; 1.0535x over previous
#include <cuda_runtime.h>
#include <cuda_fp16.h>
#include <cstdint>

#define NN 50000
#define NE 800000
#define CAP 96         // per-node bucket capacity (Poisson(16) max deg ~45)
#define TILES 391      // ceil(50000/128)

// ---------------- scratch (device globals: no allocs allowed) ----------------
__device__ int    g_cnt[NN];
__device__ float  g_rinv[NN];
__device__ int    g_bkt[NN * CAP];
__device__ float  g_sumw[NN];
__device__ __half g_h2s[NN * 128];     // fp16 copy of h, PRE-SCALED by rinv[row]
__device__ __half g_agg[NN * 128];     // aggregated features, fp16 row-major
__device__ __half g_Bh[128 * 128];     // W fp16 row-major: Bh[n][k] = W[n][k]

__device__ __forceinline__ unsigned h2u(__half2 v) {
    return *reinterpret_cast<unsigned*>(&v);
}
__device__ __forceinline__ uint32_t smem_u32(const void* p) {
    uint32_t a;
    asm("{ .reg .u64 t; cvta.to.shared.u64 t, %1; cvt.u32.u64 %0, t; }" : "=r"(a) : "l"(p));
    return a;
}

// ---------------- init: zero counters + W -> fp16 ----------------
__global__ void k_init(const float* __restrict__ W) {
    int i = blockIdx.x * 256 + threadIdx.x;      // 196*256 = 50176
    if (i < NN) g_cnt[i] = 0;
    if (i < 128 * 128) g_Bh[i] = __float2half(W[i]);
}

// ---------------- fill buckets (counts degrees as a side effect) ----------------
__global__ void k_fill(const int* __restrict__ ed) {
    int e = blockIdx.x * 256 + threadIdx.x;
    if (e < NE) {
        int s = ed[e];
        int d = ed[NE + e];
        int p = atomicAdd(&g_cnt[d], 1);
        if (p < CAP) g_bkt[d * CAP + p] = s;
    }
}

// ---------------- convert (fused rinv): h2s[row][c] = fp16(h[row][c]*rinv[row]) ----------------
__global__ void k_conv(const float* __restrict__ h) {
    int i = blockIdx.x * 256 + threadIdx.x;      // 3125*256 = 800000
    int node = i >> 4;                           // 16 threads per 128-col row
    float rv = rsqrtf((float)(g_cnt[node] + 1));
    if ((i & 15) == 0) g_rinv[node] = rv;
    size_t base = (size_t)i * 8;
    float4 f0 = *(const float4*)(h + base);
    float4 f1 = *(const float4*)(h + base + 4);
    uint4 pack;
    pack.x = h2u(__floats2half2_rn(rv * f0.x, rv * f0.y));
    pack.y = h2u(__floats2half2_rn(rv * f0.z, rv * f0.w));
    pack.z = h2u(__floats2half2_rn(rv * f1.x, rv * f1.y));
    pack.w = h2u(__floats2half2_rn(rv * f1.z, rv * f1.w));
    *(uint4*)(g_h2s + base) = pack;
}

// ---------------- aggregation: TWO warps per dst node ----------------
// Warp pair (half=0,1) splits the neighbor groups (even/odd); partials combined
// in smem. Lane owns cols {2l,2l+1, 64+2l,65+2l}; single-line half2 loads;
// fp32 accumulation; index prefetch pipeline.
__global__ void k_gather() {
    __shared__ float smA[4][128];
    __shared__ float smSR[4];
    int tid = threadIdx.x;
    int w = tid >> 5, lane = tid & 31;
    int pair = w >> 1, half = w & 1;
    int node = blockIdx.x * 4 + pair;        // 12500*4 = 50000 exactly

    float acc0, acc1, acc2, acc3;
    if (half == 0) {                          // self term on warp 0
        const __half2* hrow = (const __half2*)(g_h2s + (size_t)node * 128);
        float2 a0 = __half22float2(hrow[lane]);
        float2 a1 = __half22float2(hrow[lane + 32]);
        acc0 = a0.x; acc1 = a0.y; acc2 = a1.x; acc3 = a1.y;
    } else {
        acc0 = acc1 = acc2 = acc3 = 0.f;
    }
    float sr = 0.f;

    int n = g_cnt[node];
    if (n > CAP) n = CAP;
    const int4* bk4 = (const int4*)(g_bkt + node * CAP);
    const int*  bk  = g_bkt + node * CAP;
    int nq = n >> 2;                         // full groups of 4

    // this warp's groups: q = half, half+2, ...
    if (half < nq) {
        int4 cur = bk4[half];
        for (int q = half; q < nq; q += 2) {
            int qn = q + 2 < (CAP / 4) ? q + 2 : (CAP / 4) - 1;
            int4 nxt = bk4[qn];              // prefetch next group's indices
            float r0 = g_rinv[cur.x], r1 = g_rinv[cur.y];
            float r2 = g_rinv[cur.z], r3 = g_rinv[cur.w];
            const __half2* p0 = (const __half2*)(g_h2s + (size_t)cur.x * 128);
            const __half2* p1 = (const __half2*)(g_h2s + (size_t)cur.y * 128);
            const __half2* p2 = (const __half2*)(g_h2s + (size_t)cur.z * 128);
            const __half2* p3 = (const __half2*)(g_h2s + (size_t)cur.w * 128);
            __half2 x00 = p0[lane], x01 = p0[lane + 32];
            __half2 x10 = p1[lane], x11 = p1[lane + 32];
            __half2 x20 = p2[lane], x21 = p2[lane + 32];
            __half2 x30 = p3[lane], x31 = p3[lane + 32];
            sr += (r0 + r1) + (r2 + r3);
            float2 f;
            f = __half22float2(x00); acc0 += f.x; acc1 += f.y;
            f = __half22float2(x01); acc2 += f.x; acc3 += f.y;
            f = __half22float2(x10); acc0 += f.x; acc1 += f.y;
            f = __half22float2(x11); acc2 += f.x; acc3 += f.y;
            f = __half22float2(x20); acc0 += f.x; acc1 += f.y;
            f = __half22float2(x21); acc2 += f.x; acc3 += f.y;
            f = __half22float2(x30); acc0 += f.x; acc1 += f.y;
            f = __half22float2(x31); acc2 += f.x; acc3 += f.y;
            cur = nxt;
        }
    }
    if (half == 1) {                          // tail scalars on warp 1
        for (int j = nq * 4; j < n; j++) {
            int s = bk[j];
            const __half2* p = (const __half2*)(g_h2s + (size_t)s * 128);
            float2 f0 = __half22float2(p[lane]);
            float2 f1 = __half22float2(p[lane + 32]);
            sr += g_rinv[s];
            acc0 += f0.x; acc1 += f0.y;
            acc2 += f1.x; acc3 += f1.y;
        }
        // publish warp-1 partials
        float4 v = {acc0, acc1, acc2, acc3};
        *(float4*)(&smA[pair][lane * 4]) = v;
        if (lane == 0) {
            // reduce sr across... sr is uniform per warp (broadcast loads) -> lane0 value is fine
            smSR[pair] = sr;
        }
    }
    __syncthreads();

    if (half == 0) {
        float4 v = *(const float4*)(&smA[pair][lane * 4]);
        acc0 += v.x; acc1 += v.y; acc2 += v.z; acc3 += v.w;
        sr += smSR[pair];
        float rd = g_rinv[node];
        __half* orow = g_agg + (size_t)node * 128;
        *(unsigned*)(orow + 2 * lane)      = h2u(__floats2half2_rn(rd * acc0, rd * acc1));
        *(unsigned*)(orow + 64 + 2 * lane) = h2u(__floats2half2_rn(rd * acc2, rd * acc3));
        if (lane == 0) g_sumw[node] = rd * (sr + rd);
    }
}

// ---------------- HMMA GEMM: out[n,c] = agg[n,:] . W[c,:] + sumw[n]*b[c] ----------------
// Padded smem stride 136 halfs (272 B): ldmatrix rows land on distinct 16B banks.
#define ASTRIDE 136
#define SM_BYTES (2 * 128 * ASTRIDE * 2)   // A + B staging, 69632 B

__global__ void __launch_bounds__(256, 1)
k_mm(const float* __restrict__ bvec, float* __restrict__ out) {
    extern __shared__ __half smem[];
    __half* sA = smem;                       // [128][ASTRIDE]
    __half* sB = smem + 128 * ASTRIDE;       // [128][ASTRIDE]  (n x k)
    int tid = threadIdx.x, wrp = tid >> 5, lane = tid & 31;
    int t = blockIdx.x;

    // stage A (clamp OOB rows) and B; 16B chunks, conflict-free
    for (int i = tid; i < 2048; i += 256) {
        int r = i >> 4, cp = i & 15;
        int node = t * 128 + r;
        if (node >= NN) node = NN - 1;
        *(uint4*)(sA + r * ASTRIDE + cp * 8) =
            *(const uint4*)(g_agg + (size_t)node * 128 + cp * 8);
        *(uint4*)(sB + r * ASTRIDE + cp * 8) =
            *(const uint4*)(g_Bh + (size_t)r * 128 + cp * 8);
    }
    __syncthreads();

    int mbase = (wrp & 3) * 32;     // 4 warps over M
    int nbase = (wrp >> 2) * 64;    // 2 warps over N

    float c[2][8][4];
    #pragma unroll
    for (int mt = 0; mt < 2; mt++)
        #pragma unroll
        for (int nt = 0; nt < 8; nt++)
            #pragma unroll
            for (int q = 0; q < 4; q++) c[mt][nt][q] = 0.f;

    uint32_t aAddrBase = smem_u32(sA);
    uint32_t bAddrBase = smem_u32(sB);
    int aRow = lane & 15;
    int aK8  = (lane >> 4) << 3;
    int bRowSel = (lane & 7) + ((lane >> 4) << 3);
    int bK8  = ((lane >> 3) & 1) << 3;

    #pragma unroll
    for (int k = 0; k < 8; k++) {
        int kbase = k * 16;
        uint32_t a[2][4];
        #pragma unroll
        for (int mt = 0; mt < 2; mt++) {
            uint32_t addr = aAddrBase +
                ((mbase + mt * 16 + aRow) * ASTRIDE + kbase + aK8) * 2;
            asm volatile("ldmatrix.sync.aligned.m8n8.x4.shared.b16 {%0,%1,%2,%3}, [%4];"
                         : "=r"(a[mt][0]), "=r"(a[mt][1]), "=r"(a[mt][2]), "=r"(a[mt][3])
                         : "r"(addr));
        }
        uint32_t bf[8][2];
        #pragma unroll
        for (int p = 0; p < 4; p++) {
            uint32_t addr = bAddrBase +
                ((nbase + p * 16 + bRowSel) * ASTRIDE + kbase + bK8) * 2;
            asm volatile("ldmatrix.sync.aligned.m8n8.x4.shared.b16 {%0,%1,%2,%3}, [%4];"
                         : "=r"(bf[2 * p][0]), "=r"(bf[2 * p][1]),
                           "=r"(bf[2 * p + 1][0]), "=r"(bf[2 * p + 1][1])
                         : "r"(addr));
        }
        #pragma unroll
        for (int mt = 0; mt < 2; mt++)
            #pragma unroll
            for (int nt = 0; nt < 8; nt++)
                asm volatile(
                    "mma.sync.aligned.m16n8k16.row.col.f32.f16.f16.f32 "
                    "{%0,%1,%2,%3}, {%4,%5,%6,%7}, {%8,%9}, {%0,%1,%2,%3};"
                    : "+f"(c[mt][nt][0]), "+f"(c[mt][nt][1]),
                      "+f"(c[mt][nt][2]), "+f"(c[mt][nt][3])
                    : "r"(a[mt][0]), "r"(a[mt][1]), "r"(a[mt][2]), "r"(a[mt][3]),
                      "r"(bf[nt][0]), "r"(bf[nt][1]));
    }

    // epilogue: direct STG with sumw*bias
    #pragma unroll
    for (int mt = 0; mt < 2; mt++) {
        int r0 = mbase + mt * 16 + (lane >> 2);
        int node0 = t * 128 + r0;
        int node1 = node0 + 8;
        float s0 = (node0 < NN) ? g_sumw[node0] : 0.f;
        float s1 = (node1 < NN) ? g_sumw[node1] : 0.f;
        #pragma unroll
        for (int nt = 0; nt < 8; nt++) {
            int col = nbase + nt * 8 + (lane & 3) * 2;
            float2 bb = *(const float2*)(bvec + col);
            if (node0 < NN) {
                float2 v = { c[mt][nt][0] + s0 * bb.x, c[mt][nt][1] + s0 * bb.y };
                *(float2*)(out + (size_t)node0 * 128 + col) = v;
            }
            if (node1 < NN) {
                float2 v = { c[mt][nt][2] + s1 * bb.x, c[mt][nt][3] + s1 * bb.y };
                *(float2*)(out + (size_t)node1 * 128 + col) = v;
            }
        }
    }
}

// ---------------- launch ----------------
extern "C" void kernel_launch(void* const* d_in, const int* in_sizes, int n_in,
                              void* d_out, int out_size) {
    const float* h = nullptr;
    const float* W = nullptr;
    const float* b = nullptr;
    const int*   ed = nullptr;
    for (int i = 0; i < n_in; i++) {
        switch (in_sizes[i]) {
            case NN * 128:  h  = (const float*)d_in[i]; break;      // 6400000
            case 128 * 128: W  = (const float*)d_in[i]; break;      // 16384
            case 128:       b  = (const float*)d_in[i]; break;      // 128
            case 2 * NE:    ed = (const int*)d_in[i]; break;        // 1600000 int32
        }
    }
    float* out = (float*)d_out;

    cudaFuncSetAttribute(k_mm, cudaFuncAttributeMaxDynamicSharedMemorySize, SM_BYTES);

    k_init   <<<196, 256>>>(W);
    k_fill   <<<3125, 256>>>(ed);
    k_conv   <<<3125, 256>>>(h);
    k_gather <<<12500, 256>>>();
    k_mm     <<<TILES, 256, SM_BYTES>>>(b, out);
}

// round 15
// speedup vs baseline: 1.1190x; 1.0622x over previous
#include <cuda_runtime.h>
#include <cuda_fp16.h>
#include <cstdint>

#define NN 50000
#define NE 800000
#define CAP 96         // per-node bucket capacity (Poisson(16) max deg ~45)
#define TILES 391      // ceil(50000/128)

// ---------------- scratch (device globals: no allocs allowed) ----------------
__device__ int    g_cnt[NN];
__device__ float  g_rinv[NN];
__device__ int    g_bkt[NN * CAP];
__device__ float  g_sumw[NN];
__device__ __half g_h2s[NN * 128];     // fp16 copy of h, PRE-SCALED by rinv[row]
__device__ __half g_agg[NN * 128];     // aggregated features, fp16 row-major
__device__ __half g_Bh[128 * 128];     // W fp16 row-major: Bh[n][k] = W[n][k]

__device__ __forceinline__ unsigned h2u(__half2 v) {
    return *reinterpret_cast<unsigned*>(&v);
}
__device__ __forceinline__ uint32_t smem_u32(const void* p) {
    uint32_t a;
    asm("{ .reg .u64 t; cvta.to.shared.u64 t, %1; cvt.u32.u64 %0, t; }" : "=r"(a) : "l"(p));
    return a;
}

// ---------------- init: zero counters + W -> fp16 ----------------
__global__ void k_init(const float* __restrict__ W) {
    int i = blockIdx.x * 256 + threadIdx.x;      // 196*256 = 50176
    if (i < NN) g_cnt[i] = 0;
    if (i < 128 * 128) g_Bh[i] = __float2half(W[i]);
}

// ---------------- fill buckets (counts degrees as a side effect) ----------------
__global__ void k_fill(const int* __restrict__ ed) {
    int e = blockIdx.x * 256 + threadIdx.x;
    if (e < NE) {
        int s = ed[e];
        int d = ed[NE + e];
        int p = atomicAdd(&g_cnt[d], 1);
        if (p < CAP) g_bkt[d * CAP + p] = s;
    }
}

// ---------------- convert (fused rinv): h2s[row][c] = fp16(h[row][c]*rinv[row]) ----------------
__global__ void k_conv(const float* __restrict__ h) {
    int i = blockIdx.x * 256 + threadIdx.x;      // 3125*256 = 800000
    int node = i >> 4;                           // 16 threads per 128-col row
    float rv = rsqrtf((float)(g_cnt[node] + 1));
    if ((i & 15) == 0) g_rinv[node] = rv;
    size_t base = (size_t)i * 8;
    float4 f0 = *(const float4*)(h + base);
    float4 f1 = *(const float4*)(h + base + 4);
    uint4 pack;
    pack.x = h2u(__floats2half2_rn(rv * f0.x, rv * f0.y));
    pack.y = h2u(__floats2half2_rn(rv * f0.z, rv * f0.w));
    pack.z = h2u(__floats2half2_rn(rv * f1.x, rv * f1.y));
    pack.w = h2u(__floats2half2_rn(rv * f1.z, rv * f1.w));
    *(uint4*)(g_h2s + base) = pack;
}

// ---------------- aggregation: one warp per dst node, distance-2 index prefetch ----------------
// agg[d] = rinv[d] * ( h2s[d] + sum_s h2s[s] );  sumw[d] = rinv[d]*(sum_s rinv[s] + rinv[d])
__global__ void k_gather() {
    int tid = threadIdx.x;
    int w = tid >> 5, lane = tid & 31;
    int node = blockIdx.x * 8 + w;           // 6250*8 = 50000 exactly

    const __half2* hrow = (const __half2*)(g_h2s + (size_t)node * 128);
    float2 a0 = __half22float2(hrow[lane]);
    float2 a1 = __half22float2(hrow[lane + 32]);
    float acc0 = a0.x, acc1 = a0.y, acc2 = a1.x, acc3 = a1.y;  // self term
    float sr = 0.f;

    int n = g_cnt[node];
    if (n > CAP) n = CAP;
    const int4* bk4 = (const int4*)(g_bkt + node * CAP);
    const int*  bk  = g_bkt + node * CAP;
    int nq = n >> 2;                         // full groups of 4

    if (nq > 0) {
        // distance-2 software pipeline on index groups (clamped: stays in bucket)
        int4 cur = bk4[0];
        int4 nxt = bk4[1 < (CAP / 4) ? 1 : 0];
        for (int q = 0; q < nq; q++) {
            int q2 = q + 2 < (CAP / 4) ? q + 2 : (CAP / 4) - 1;
            int4 nxt2 = bk4[q2];             // prefetch, 2 groups ahead
            float r0 = g_rinv[cur.x], r1 = g_rinv[cur.y];
            float r2 = g_rinv[cur.z], r3 = g_rinv[cur.w];
            const __half2* p0 = (const __half2*)(g_h2s + (size_t)cur.x * 128);
            const __half2* p1 = (const __half2*)(g_h2s + (size_t)cur.y * 128);
            const __half2* p2 = (const __half2*)(g_h2s + (size_t)cur.z * 128);
            const __half2* p3 = (const __half2*)(g_h2s + (size_t)cur.w * 128);
            __half2 x00 = p0[lane], x01 = p0[lane + 32];
            __half2 x10 = p1[lane], x11 = p1[lane + 32];
            __half2 x20 = p2[lane], x21 = p2[lane + 32];
            __half2 x30 = p3[lane], x31 = p3[lane + 32];
            sr += (r0 + r1) + (r2 + r3);
            float2 f;
            f = __half22float2(x00); acc0 += f.x; acc1 += f.y;
            f = __half22float2(x01); acc2 += f.x; acc3 += f.y;
            f = __half22float2(x10); acc0 += f.x; acc1 += f.y;
            f = __half22float2(x11); acc2 += f.x; acc3 += f.y;
            f = __half22float2(x20); acc0 += f.x; acc1 += f.y;
            f = __half22float2(x21); acc2 += f.x; acc3 += f.y;
            f = __half22float2(x30); acc0 += f.x; acc1 += f.y;
            f = __half22float2(x31); acc2 += f.x; acc3 += f.y;
            cur = nxt;
            nxt = nxt2;
        }
    }
    for (int j = nq * 4; j < n; j++) {
        int s = bk[j];
        const __half2* p = (const __half2*)(g_h2s + (size_t)s * 128);
        float2 f0 = __half22float2(p[lane]);
        float2 f1 = __half22float2(p[lane + 32]);
        sr += g_rinv[s];
        acc0 += f0.x; acc1 += f0.y;
        acc2 += f1.x; acc3 += f1.y;
    }

    float rd = g_rinv[node];
    __half* orow = g_agg + (size_t)node * 128;
    *(unsigned*)(orow + 2 * lane)      = h2u(__floats2half2_rn(rd * acc0, rd * acc1));
    *(unsigned*)(orow + 64 + 2 * lane) = h2u(__floats2half2_rn(rd * acc2, rd * acc3));
    if (lane == 0) g_sumw[node] = rd * (sr + rd);
}

// ---------------- HMMA GEMM: out[n,c] = agg[n,:] . W[c,:] + sumw[n]*b[c] ----------------
// Padded smem stride 136 halfs (272 B): ldmatrix rows land on distinct 16B banks.
#define ASTRIDE 136
#define SM_BYTES (2 * 128 * ASTRIDE * 2)   // A + B staging, 69632 B

__global__ void __launch_bounds__(256, 1)
k_mm(const float* __restrict__ bvec, float* __restrict__ out) {
    extern __shared__ __half smem[];
    __half* sA = smem;                       // [128][ASTRIDE]
    __half* sB = smem + 128 * ASTRIDE;       // [128][ASTRIDE]  (n x k)
    int tid = threadIdx.x, wrp = tid >> 5, lane = tid & 31;
    int t = blockIdx.x;

    // stage A (clamp OOB rows) and B; 16B chunks, conflict-free
    for (int i = tid; i < 2048; i += 256) {
        int r = i >> 4, cp = i & 15;
        int node = t * 128 + r;
        if (node >= NN) node = NN - 1;
        *(uint4*)(sA + r * ASTRIDE + cp * 8) =
            *(const uint4*)(g_agg + (size_t)node * 128 + cp * 8);
        *(uint4*)(sB + r * ASTRIDE + cp * 8) =
            *(const uint4*)(g_Bh + (size_t)r * 128 + cp * 8);
    }
    __syncthreads();

    int mbase = (wrp & 3) * 32;     // 4 warps over M
    int nbase = (wrp >> 2) * 64;    // 2 warps over N

    float c[2][8][4];
    #pragma unroll
    for (int mt = 0; mt < 2; mt++)
        #pragma unroll
        for (int nt = 0; nt < 8; nt++)
            #pragma unroll
            for (int q = 0; q < 4; q++) c[mt][nt][q] = 0.f;

    uint32_t aAddrBase = smem_u32(sA);
    uint32_t bAddrBase = smem_u32(sB);
    int aRow = lane & 15;
    int aK8  = (lane >> 4) << 3;
    int bRowSel = (lane & 7) + ((lane >> 4) << 3);
    int bK8  = ((lane >> 3) & 1) << 3;

    #pragma unroll
    for (int k = 0; k < 8; k++) {
        int kbase = k * 16;
        uint32_t a[2][4];
        #pragma unroll
        for (int mt = 0; mt < 2; mt++) {
            uint32_t addr = aAddrBase +
                ((mbase + mt * 16 + aRow) * ASTRIDE + kbase + aK8) * 2;
            asm volatile("ldmatrix.sync.aligned.m8n8.x4.shared.b16 {%0,%1,%2,%3}, [%4];"
                         : "=r"(a[mt][0]), "=r"(a[mt][1]), "=r"(a[mt][2]), "=r"(a[mt][3])
                         : "r"(addr));
        }
        uint32_t bf[8][2];
        #pragma unroll
        for (int p = 0; p < 4; p++) {
            uint32_t addr = bAddrBase +
                ((nbase + p * 16 + bRowSel) * ASTRIDE + kbase + bK8) * 2;
            asm volatile("ldmatrix.sync.aligned.m8n8.x4.shared.b16 {%0,%1,%2,%3}, [%4];"
                         : "=r"(bf[2 * p][0]), "=r"(bf[2 * p][1]),
                           "=r"(bf[2 * p + 1][0]), "=r"(bf[2 * p + 1][1])
                         : "r"(addr));
        }
        #pragma unroll
        for (int mt = 0; mt < 2; mt++)
            #pragma unroll
            for (int nt = 0; nt < 8; nt++)
                asm volatile(
                    "mma.sync.aligned.m16n8k16.row.col.f32.f16.f16.f32 "
                    "{%0,%1,%2,%3}, {%4,%5,%6,%7}, {%8,%9}, {%0,%1,%2,%3};"
                    : "+f"(c[mt][nt][0]), "+f"(c[mt][nt][1]),
                      "+f"(c[mt][nt][2]), "+f"(c[mt][nt][3])
                    : "r"(a[mt][0]), "r"(a[mt][1]), "r"(a[mt][2]), "r"(a[mt][3]),
                      "r"(bf[nt][0]), "r"(bf[nt][1]));
    }

    // epilogue: direct STG with sumw*bias
    #pragma unroll
    for (int mt = 0; mt < 2; mt++) {
        int r0 = mbase + mt * 16 + (lane >> 2);
        int node0 = t * 128 + r0;
        int node1 = node0 + 8;
        float s0 = (node0 < NN) ? g_sumw[node0] : 0.f;
        float s1 = (node1 < NN) ? g_sumw[node1] : 0.f;
        #pragma unroll
        for (int nt = 0; nt < 8; nt++) {
            int col = nbase + nt * 8 + (lane & 3) * 2;
            float2 bb = *(const float2*)(bvec + col);
            if (node0 < NN) {
                float2 v = { c[mt][nt][0] + s0 * bb.x, c[mt][nt][1] + s0 * bb.y };
                *(float2*)(out + (size_t)node0 * 128 + col) = v;
            }
            if (node1 < NN) {
                float2 v = { c[mt][nt][2] + s1 * bb.x, c[mt][nt][3] + s1 * bb.y };
                *(float2*)(out + (size_t)node1 * 128 + col) = v;
            }
        }
    }
}

// ---------------- launch ----------------
extern "C" void kernel_launch(void* const* d_in, const int* in_sizes, int n_in,
                              void* d_out, int out_size) {
    const float* h = nullptr;
    const float* W = nullptr;
    const float* b = nullptr;
    const int*   ed = nullptr;
    for (int i = 0; i < n_in; i++) {
        switch (in_sizes[i]) {
            case NN * 128:  h  = (const float*)d_in[i]; break;      // 6400000
            case 128 * 128: W  = (const float*)d_in[i]; break;      // 16384
            case 128:       b  = (const float*)d_in[i]; break;      // 128
            case 2 * NE:    ed = (const int*)d_in[i]; break;        // 1600000 int32
        }
    }
    float* out = (float*)d_out;

    cudaFuncSetAttribute(k_mm, cudaFuncAttributeMaxDynamicSharedMemorySize, SM_BYTES);

    k_init   <<<196, 256>>>(W);
    k_fill   <<<3125, 256>>>(ed);
    k_conv   <<<3125, 256>>>(h);
    k_gather <<<6250, 256>>>();
    k_mm     <<<TILES, 256, SM_BYTES>>>(b, out);
}

// round 16
// speedup vs baseline: 1.1842x; 1.0583x over previous
#include <cuda_runtime.h>
#include <cuda_fp16.h>
#include <cstdint>

#define NN 50000
#define NE 800000
#define CAP 96         // per-node bucket capacity (Poisson(16) max deg ~45)
#define TILES 391      // ceil(50000/128)

// ---------------- scratch (device globals: no allocs allowed) ----------------
__device__ int    g_cnt[NN];
__device__ float  g_rinv[NN];
__device__ int    g_bkt[NN * CAP];
__device__ float  g_sumw[NN];
__device__ __half g_h2s[NN * 128];     // fp16 copy of h, PRE-SCALED by rinv[row]
__device__ __half g_agg[NN * 128];     // aggregated features, fp16 row-major
__device__ __half g_Bh[128 * 128];     // W fp16 row-major: Bh[n][k] = W[n][k]

__device__ __forceinline__ unsigned h2u(__half2 v) {
    return *reinterpret_cast<unsigned*>(&v);
}
__device__ __forceinline__ uint32_t smem_u32(const void* p) {
    uint32_t a;
    asm("{ .reg .u64 t; cvta.to.shared.u64 t, %1; cvt.u32.u64 %0, t; }" : "=r"(a) : "l"(p));
    return a;
}

// ---------------- init: zero counters + W -> fp16 ----------------
__global__ void k_init(const float* __restrict__ W) {
    int i = blockIdx.x * 256 + threadIdx.x;      // 196*256 = 50176
    if (i < NN) g_cnt[i] = 0;
    if (i < 128 * 128) g_Bh[i] = __float2half(W[i]);
}

// ---------------- fill buckets (counts degrees as a side effect) ----------------
__global__ void k_fill(const int* __restrict__ ed) {
    int e = blockIdx.x * 256 + threadIdx.x;
    if (e < NE) {
        int s = ed[e];
        int d = ed[NE + e];
        int p = atomicAdd(&g_cnt[d], 1);
        if (p < CAP) g_bkt[d * CAP + p] = s;
    }
}

// ---------------- convert (fused rinv): h2s[row][c] = fp16(h[row][c]*rinv[row]) ----------------
// 16 floats per thread: 4 independent LDG.128 in flight (latency hiding).
__global__ void k_conv(const float* __restrict__ h) {
    int i = blockIdx.x * 256 + threadIdx.x;      // 1563*256 >= 400000
    if (i >= 400000) return;
    int node = i >> 3;                           // 8 threads per 128-col row
    float rv = rsqrtf((float)(g_cnt[node] + 1));
    if ((i & 7) == 0) g_rinv[node] = rv;
    size_t base = (size_t)i * 16;
    float4 f0 = *(const float4*)(h + base);
    float4 f1 = *(const float4*)(h + base + 4);
    float4 f2 = *(const float4*)(h + base + 8);
    float4 f3 = *(const float4*)(h + base + 12);
    uint4 pa, pb;
    pa.x = h2u(__floats2half2_rn(rv * f0.x, rv * f0.y));
    pa.y = h2u(__floats2half2_rn(rv * f0.z, rv * f0.w));
    pa.z = h2u(__floats2half2_rn(rv * f1.x, rv * f1.y));
    pa.w = h2u(__floats2half2_rn(rv * f1.z, rv * f1.w));
    pb.x = h2u(__floats2half2_rn(rv * f2.x, rv * f2.y));
    pb.y = h2u(__floats2half2_rn(rv * f2.z, rv * f2.w));
    pb.z = h2u(__floats2half2_rn(rv * f3.x, rv * f3.y));
    pb.w = h2u(__floats2half2_rn(rv * f3.z, rv * f3.w));
    *(uint4*)(g_h2s + base)     = pa;
    *(uint4*)(g_h2s + base + 8) = pb;
}

// ---------------- aggregation: one warp per dst node ----------------
// R12 load shape (2x single-line half2 per row) + fp16 HADD2 accumulation
// split across two accumulator pairs (even/odd edges) for precision + ILP.
// agg[d] = rinv[d] * ( h2s[d] + sum_s h2s[s] );  sumw[d] = rinv[d]*(sum_s rinv[s] + rinv[d])
__global__ void k_gather() {
    int tid = threadIdx.x;
    int w = tid >> 5, lane = tid & 31;
    int node = blockIdx.x * 8 + w;           // 6250*8 = 50000 exactly

    const __half2* hrow = (const __half2*)(g_h2s + (size_t)node * 128);
    __half2 accA0 = hrow[lane];              // cols 2l,2l+1   (self term)
    __half2 accB0 = hrow[lane + 32];         // cols 64+2l,65+2l
    __half2 accA1 = __float2half2_rn(0.f);
    __half2 accB1 = __float2half2_rn(0.f);
    float sr = 0.f;

    int n = g_cnt[node];
    if (n > CAP) n = CAP;
    const int4* bk4 = (const int4*)(g_bkt + node * CAP);
    const int*  bk  = g_bkt + node * CAP;
    int nq = n >> 2;                         // full groups of 4

    if (nq > 0) {
        int4 cur = bk4[0];
        for (int q = 0; q < nq; q++) {
            int qn = q + 1 < (CAP / 4) ? q + 1 : (CAP / 4) - 1;
            int4 nxt = bk4[qn];              // prefetch next indices
            float r0 = g_rinv[cur.x], r1 = g_rinv[cur.y];
            float r2 = g_rinv[cur.z], r3 = g_rinv[cur.w];
            const __half2* p0 = (const __half2*)(g_h2s + (size_t)cur.x * 128);
            const __half2* p1 = (const __half2*)(g_h2s + (size_t)cur.y * 128);
            const __half2* p2 = (const __half2*)(g_h2s + (size_t)cur.z * 128);
            const __half2* p3 = (const __half2*)(g_h2s + (size_t)cur.w * 128);
            __half2 x00 = p0[lane], x01 = p0[lane + 32];
            __half2 x10 = p1[lane], x11 = p1[lane + 32];
            __half2 x20 = p2[lane], x21 = p2[lane + 32];
            __half2 x30 = p3[lane], x31 = p3[lane + 32];
            sr += (r0 + r1) + (r2 + r3);
            accA0 = __hadd2(accA0, x00); accB0 = __hadd2(accB0, x01);
            accA1 = __hadd2(accA1, x10); accB1 = __hadd2(accB1, x11);
            accA0 = __hadd2(accA0, x20); accB0 = __hadd2(accB0, x21);
            accA1 = __hadd2(accA1, x30); accB1 = __hadd2(accB1, x31);
            cur = nxt;
        }
    }
    for (int j = nq * 4; j < n; j++) {
        int s = bk[j];
        const __half2* p = (const __half2*)(g_h2s + (size_t)s * 128);
        __half2 v0 = p[lane], v1 = p[lane + 32];
        sr += g_rinv[s];
        accA1 = __hadd2(accA1, v0);
        accB1 = __hadd2(accB1, v1);
    }

    // combine accumulator pairs in fp32, scale by rd, round once to fp16
    float rd = g_rinv[node];
    float2 fa0 = __half22float2(accA0), fa1 = __half22float2(accA1);
    float2 fb0 = __half22float2(accB0), fb1 = __half22float2(accB1);
    float o0 = rd * (fa0.x + fa1.x), o1 = rd * (fa0.y + fa1.y);
    float o2 = rd * (fb0.x + fb1.x), o3 = rd * (fb0.y + fb1.y);
    __half* orow = g_agg + (size_t)node * 128;
    *(unsigned*)(orow + 2 * lane)      = h2u(__floats2half2_rn(o0, o1));
    *(unsigned*)(orow + 64 + 2 * lane) = h2u(__floats2half2_rn(o2, o3));
    if (lane == 0) g_sumw[node] = rd * (sr + rd);
}

// ---------------- HMMA GEMM: out[n,c] = agg[n,:] . W[c,:] + sumw[n]*b[c] ----------------
// Padded smem stride 136 halfs (272 B): ldmatrix rows land on distinct 16B banks.
#define ASTRIDE 136
#define SM_BYTES (2 * 128 * ASTRIDE * 2)   // A + B staging, 69632 B

__global__ void __launch_bounds__(256, 1)
k_mm(const float* __restrict__ bvec, float* __restrict__ out) {
    extern __shared__ __half smem[];
    __half* sA = smem;                       // [128][ASTRIDE]
    __half* sB = smem + 128 * ASTRIDE;       // [128][ASTRIDE]  (n x k)
    int tid = threadIdx.x, wrp = tid >> 5, lane = tid & 31;
    int t = blockIdx.x;

    // stage A (clamp OOB rows) and B; 16B chunks, conflict-free
    for (int i = tid; i < 2048; i += 256) {
        int r = i >> 4, cp = i & 15;
        int node = t * 128 + r;
        if (node >= NN) node = NN - 1;
        *(uint4*)(sA + r * ASTRIDE + cp * 8) =
            *(const uint4*)(g_agg + (size_t)node * 128 + cp * 8);
        *(uint4*)(sB + r * ASTRIDE + cp * 8) =
            *(const uint4*)(g_Bh + (size_t)r * 128 + cp * 8);
    }
    __syncthreads();

    int mbase = (wrp & 3) * 32;     // 4 warps over M
    int nbase = (wrp >> 2) * 64;    // 2 warps over N

    float c[2][8][4];
    #pragma unroll
    for (int mt = 0; mt < 2; mt++)
        #pragma unroll
        for (int nt = 0; nt < 8; nt++)
            #pragma unroll
            for (int q = 0; q < 4; q++) c[mt][nt][q] = 0.f;

    uint32_t aAddrBase = smem_u32(sA);
    uint32_t bAddrBase = smem_u32(sB);
    int aRow = lane & 15;
    int aK8  = (lane >> 4) << 3;
    int bRowSel = (lane & 7) + ((lane >> 4) << 3);
    int bK8  = ((lane >> 3) & 1) << 3;

    #pragma unroll
    for (int k = 0; k < 8; k++) {
        int kbase = k * 16;
        uint32_t a[2][4];
        #pragma unroll
        for (int mt = 0; mt < 2; mt++) {
            uint32_t addr = aAddrBase +
                ((mbase + mt * 16 + aRow) * ASTRIDE + kbase + aK8) * 2;
            asm volatile("ldmatrix.sync.aligned.m8n8.x4.shared.b16 {%0,%1,%2,%3}, [%4];"
                         : "=r"(a[mt][0]), "=r"(a[mt][1]), "=r"(a[mt][2]), "=r"(a[mt][3])
                         : "r"(addr));
        }
        uint32_t bf[8][2];
        #pragma unroll
        for (int p = 0; p < 4; p++) {
            uint32_t addr = bAddrBase +
                ((nbase + p * 16 + bRowSel) * ASTRIDE + kbase + bK8) * 2;
            asm volatile("ldmatrix.sync.aligned.m8n8.x4.shared.b16 {%0,%1,%2,%3}, [%4];"
                         : "=r"(bf[2 * p][0]), "=r"(bf[2 * p][1]),
                           "=r"(bf[2 * p + 1][0]), "=r"(bf[2 * p + 1][1])
                         : "r"(addr));
        }
        #pragma unroll
        for (int mt = 0; mt < 2; mt++)
            #pragma unroll
            for (int nt = 0; nt < 8; nt++)
                asm volatile(
                    "mma.sync.aligned.m16n8k16.row.col.f32.f16.f16.f32 "
                    "{%0,%1,%2,%3}, {%4,%5,%6,%7}, {%8,%9}, {%0,%1,%2,%3};"
                    : "+f"(c[mt][nt][0]), "+f"(c[mt][nt][1]),
                      "+f"(c[mt][nt][2]), "+f"(c[mt][nt][3])
                    : "r"(a[mt][0]), "r"(a[mt][1]), "r"(a[mt][2]), "r"(a[mt][3]),
                      "r"(bf[nt][0]), "r"(bf[nt][1]));
    }

    // epilogue: direct STG with sumw*bias
    #pragma unroll
    for (int mt = 0; mt < 2; mt++) {
        int r0 = mbase + mt * 16 + (lane >> 2);
        int node0 = t * 128 + r0;
        int node1 = node0 + 8;
        float s0 = (node0 < NN) ? g_sumw[node0] : 0.f;
        float s1 = (node1 < NN) ? g_sumw[node1] : 0.f;
        #pragma unroll
        for (int nt = 0; nt < 8; nt++) {
            int col = nbase + nt * 8 + (lane & 3) * 2;
            float2 bb = *(const float2*)(bvec + col);
            if (node0 < NN) {
                float2 v = { c[mt][nt][0] + s0 * bb.x, c[mt][nt][1] + s0 * bb.y };
                *(float2*)(out + (size_t)node0 * 128 + col) = v;
            }
            if (node1 < NN) {
                float2 v = { c[mt][nt][2] + s1 * bb.x, c[mt][nt][3] + s1 * bb.y };
                *(float2*)(out + (size_t)node1 * 128 + col) = v;
            }
        }
    }
}

// ---------------- launch ----------------
extern "C" void kernel_launch(void* const* d_in, const int* in_sizes, int n_in,
                              void* d_out, int out_size) {
    const float* h = nullptr;
    const float* W = nullptr;
    const float* b = nullptr;
    const int*   ed = nullptr;
    for (int i = 0; i < n_in; i++) {
        switch (in_sizes[i]) {
            case NN * 128:  h  = (const float*)d_in[i]; break;      // 6400000
            case 128 * 128: W  = (const float*)d_in[i]; break;      // 16384
            case 128:       b  = (const float*)d_in[i]; break;      // 128
            case 2 * NE:    ed = (const int*)d_in[i]; break;        // 1600000 int32
        }
    }
    float* out = (float*)d_out;

    cudaFuncSetAttribute(k_mm, cudaFuncAttributeMaxDynamicSharedMemorySize, SM_BYTES);

    k_init   <<<196, 256>>>(W);
    k_fill   <<<3125, 256>>>(ed);
    k_conv   <<<1563, 256>>>(h);
    k_gather <<<6250, 256>>>();
    k_mm     <<<TILES, 256, SM_BYTES>>>(b, out);
}

// round 17
// speedup vs baseline: 1.2444x; 1.0509x over previous
#include <cuda_runtime.h>
#include <cuda_fp16.h>
#include <cstdint>

#define NN 50000
#define NE 800000
#define CAP 96         // per-node bucket capacity (Poisson(16) max deg ~45)
#define TILES 391      // ceil(50000/128)

// ---------------- scratch (device globals: no allocs allowed) ----------------
// g_cnt starts zero (static init) and is re-zeroed at the end of k_mm each run.
__device__ int    g_cnt[NN];
__device__ float  g_rinv[NN];
__device__ int    g_bkt[NN * CAP];
__device__ float  g_sumw[NN];
__device__ __half g_h2s[NN * 128];     // fp16 copy of h, PRE-SCALED by rinv[row]
__device__ __half g_agg[NN * 128];     // aggregated features, fp16 row-major
__device__ __half g_Bh[128 * 128];     // W fp16 row-major: Bh[n][k] = W[n][k]

__device__ __forceinline__ unsigned h2u(__half2 v) {
    return *reinterpret_cast<unsigned*>(&v);
}
__device__ __forceinline__ uint32_t smem_u32(const void* p) {
    uint32_t a;
    asm("{ .reg .u64 t; cvta.to.shared.u64 t, %1; cvt.u32.u64 %0, t; }" : "=r"(a) : "l"(p));
    return a;
}

// ---------------- fill buckets + W -> fp16 (counters pre-zeroed by prev run) ----------------
__global__ void k_fill(const int* __restrict__ ed, const float* __restrict__ W) {
    int e = blockIdx.x * 256 + threadIdx.x;
    if (e < 128 * 128) g_Bh[e] = __float2half(W[e]);
    if (e < NE) {
        int s = ed[e];
        int d = ed[NE + e];
        int p = atomicAdd(&g_cnt[d], 1);
        if (p < CAP) g_bkt[d * CAP + p] = s;
    }
}

// ---------------- convert (fused rinv): h2s[row][c] = fp16(h[row][c]*rinv[row]) ----------------
// 16 floats per thread: 4 independent LDG.128 in flight (latency hiding).
__global__ void k_conv(const float* __restrict__ h) {
    int i = blockIdx.x * 256 + threadIdx.x;      // 1563*256 >= 400000
    if (i >= 400000) return;
    int node = i >> 3;                           // 8 threads per 128-col row
    float rv = rsqrtf((float)(g_cnt[node] + 1));
    if ((i & 7) == 0) g_rinv[node] = rv;
    size_t base = (size_t)i * 16;
    float4 f0 = *(const float4*)(h + base);
    float4 f1 = *(const float4*)(h + base + 4);
    float4 f2 = *(const float4*)(h + base + 8);
    float4 f3 = *(const float4*)(h + base + 12);
    uint4 pa, pb;
    pa.x = h2u(__floats2half2_rn(rv * f0.x, rv * f0.y));
    pa.y = h2u(__floats2half2_rn(rv * f0.z, rv * f0.w));
    pa.z = h2u(__floats2half2_rn(rv * f1.x, rv * f1.y));
    pa.w = h2u(__floats2half2_rn(rv * f1.z, rv * f1.w));
    pb.x = h2u(__floats2half2_rn(rv * f2.x, rv * f2.y));
    pb.y = h2u(__floats2half2_rn(rv * f2.z, rv * f2.w));
    pb.z = h2u(__floats2half2_rn(rv * f3.x, rv * f3.y));
    pb.w = h2u(__floats2half2_rn(rv * f3.z, rv * f3.w));
    *(uint4*)(g_h2s + base)     = pa;
    *(uint4*)(g_h2s + base + 8) = pb;
}

// ---------------- aggregation: one warp per dst node ----------------
// Data-pipelined: group q+1's 8 row-loads issue while group q accumulates.
// fp16 HADD2 accumulation in two pairs; combined in fp32 at the end.
__global__ void k_gather() {
    int tid = threadIdx.x;
    int w = tid >> 5, lane = tid & 31;
    int node = blockIdx.x * 8 + w;           // 6250*8 = 50000 exactly

    const __half2* hrow = (const __half2*)(g_h2s + (size_t)node * 128);
    __half2 accA0 = hrow[lane];              // cols 2l,2l+1   (self term)
    __half2 accB0 = hrow[lane + 32];         // cols 64+2l,65+2l
    __half2 accA1 = __float2half2_rn(0.f);
    __half2 accB1 = __float2half2_rn(0.f);
    float sr = 0.f;

    int n = g_cnt[node];
    if (n > CAP) n = CAP;
    const int4* bk4 = (const int4*)(g_bkt + node * CAP);
    const int*  bk  = g_bkt + node * CAP;
    int nq = n >> 2;                         // full groups of 4

    if (nq > 0) {
        // prolog: group 0 rows + rinv in flight
        int4 cur = bk4[0];
        const __half2* c0 = (const __half2*)(g_h2s + (size_t)cur.x * 128);
        const __half2* c1 = (const __half2*)(g_h2s + (size_t)cur.y * 128);
        const __half2* c2 = (const __half2*)(g_h2s + (size_t)cur.z * 128);
        const __half2* c3 = (const __half2*)(g_h2s + (size_t)cur.w * 128);
        __half2 ya0 = c0[lane], yb0 = c0[lane + 32];
        __half2 ya1 = c1[lane], yb1 = c1[lane + 32];
        __half2 ya2 = c2[lane], yb2 = c2[lane + 32];
        __half2 ya3 = c3[lane], yb3 = c3[lane + 32];
        float rc0 = g_rinv[cur.x], rc1 = g_rinv[cur.y];
        float rc2 = g_rinv[cur.z], rc3 = g_rinv[cur.w];

        for (int q = 0; q < nq; q++) {
            // prefetch next group's rows (clamped to valid groups; last iter
            // re-loads the final group and the values are discarded)
            int qn = q + 1 < nq ? q + 1 : nq - 1;
            int4 nxt = bk4[qn];
            const __half2* n0 = (const __half2*)(g_h2s + (size_t)nxt.x * 128);
            const __half2* n1 = (const __half2*)(g_h2s + (size_t)nxt.y * 128);
            const __half2* n2 = (const __half2*)(g_h2s + (size_t)nxt.z * 128);
            const __half2* n3 = (const __half2*)(g_h2s + (size_t)nxt.w * 128);
            __half2 za0 = n0[lane], zb0 = n0[lane + 32];
            __half2 za1 = n1[lane], zb1 = n1[lane + 32];
            __half2 za2 = n2[lane], zb2 = n2[lane + 32];
            __half2 za3 = n3[lane], zb3 = n3[lane + 32];
            float rn0 = g_rinv[nxt.x], rn1 = g_rinv[nxt.y];
            float rn2 = g_rinv[nxt.z], rn3 = g_rinv[nxt.w];

            // accumulate current group (data already arrived last iteration)
            sr += (rc0 + rc1) + (rc2 + rc3);
            accA0 = __hadd2(accA0, ya0); accB0 = __hadd2(accB0, yb0);
            accA1 = __hadd2(accA1, ya1); accB1 = __hadd2(accB1, yb1);
            accA0 = __hadd2(accA0, ya2); accB0 = __hadd2(accB0, yb2);
            accA1 = __hadd2(accA1, ya3); accB1 = __hadd2(accB1, yb3);

            ya0 = za0; yb0 = zb0; ya1 = za1; yb1 = zb1;
            ya2 = za2; yb2 = zb2; ya3 = za3; yb3 = zb3;
            rc0 = rn0; rc1 = rn1; rc2 = rn2; rc3 = rn3;
        }
    }
    for (int j = nq * 4; j < n; j++) {
        int s = bk[j];
        const __half2* p = (const __half2*)(g_h2s + (size_t)s * 128);
        __half2 v0 = p[lane], v1 = p[lane + 32];
        sr += g_rinv[s];
        accA1 = __hadd2(accA1, v0);
        accB1 = __hadd2(accB1, v1);
    }

    // combine accumulator pairs in fp32, scale by rd, round once to fp16
    float rd = g_rinv[node];
    float2 fa0 = __half22float2(accA0), fa1 = __half22float2(accA1);
    float2 fb0 = __half22float2(accB0), fb1 = __half22float2(accB1);
    float o0 = rd * (fa0.x + fa1.x), o1 = rd * (fa0.y + fa1.y);
    float o2 = rd * (fb0.x + fb1.x), o3 = rd * (fb0.y + fb1.y);
    __half* orow = g_agg + (size_t)node * 128;
    *(unsigned*)(orow + 2 * lane)      = h2u(__floats2half2_rn(o0, o1));
    *(unsigned*)(orow + 64 + 2 * lane) = h2u(__floats2half2_rn(o2, o3));
    if (lane == 0) g_sumw[node] = rd * (sr + rd);
}

// ---------------- HMMA GEMM: out[n,c] = agg[n,:] . W[c,:] + sumw[n]*b[c] ----------------
// Padded smem stride 136 halfs (272 B): ldmatrix rows land on distinct 16B banks.
// Tail duty: re-zero g_cnt for the next graph replay.
#define ASTRIDE 136
#define SM_BYTES (2 * 128 * ASTRIDE * 2)   // A + B staging, 69632 B

__global__ void __launch_bounds__(256, 1)
k_mm(const float* __restrict__ bvec, float* __restrict__ out) {
    extern __shared__ __half smem[];
    __half* sA = smem;                       // [128][ASTRIDE]
    __half* sB = smem + 128 * ASTRIDE;       // [128][ASTRIDE]  (n x k)
    int tid = threadIdx.x, wrp = tid >> 5, lane = tid & 31;
    int t = blockIdx.x;

    // stage A (clamp OOB rows) and B; 16B chunks, conflict-free
    for (int i = tid; i < 2048; i += 256) {
        int r = i >> 4, cp = i & 15;
        int node = t * 128 + r;
        if (node >= NN) node = NN - 1;
        *(uint4*)(sA + r * ASTRIDE + cp * 8) =
            *(const uint4*)(g_agg + (size_t)node * 128 + cp * 8);
        *(uint4*)(sB + r * ASTRIDE + cp * 8) =
            *(const uint4*)(g_Bh + (size_t)r * 128 + cp * 8);
    }

    // re-zero degree counters for the next replay (no other kernel is running)
    {
        int gi = t * 256 + tid;              // 391*256 = 100096 >= NN
        if (gi < NN) g_cnt[gi] = 0;
    }
    __syncthreads();

    int mbase = (wrp & 3) * 32;     // 4 warps over M
    int nbase = (wrp >> 2) * 64;    // 2 warps over N

    float c[2][8][4];
    #pragma unroll
    for (int mt = 0; mt < 2; mt++)
        #pragma unroll
        for (int nt = 0; nt < 8; nt++)
            #pragma unroll
            for (int q = 0; q < 4; q++) c[mt][nt][q] = 0.f;

    uint32_t aAddrBase = smem_u32(sA);
    uint32_t bAddrBase = smem_u32(sB);
    int aRow = lane & 15;
    int aK8  = (lane >> 4) << 3;
    int bRowSel = (lane & 7) + ((lane >> 4) << 3);
    int bK8  = ((lane >> 3) & 1) << 3;

    #pragma unroll
    for (int k = 0; k < 8; k++) {
        int kbase = k * 16;
        uint32_t a[2][4];
        #pragma unroll
        for (int mt = 0; mt < 2; mt++) {
            uint32_t addr = aAddrBase +
                ((mbase + mt * 16 + aRow) * ASTRIDE + kbase + aK8) * 2;
            asm volatile("ldmatrix.sync.aligned.m8n8.x4.shared.b16 {%0,%1,%2,%3}, [%4];"
                         : "=r"(a[mt][0]), "=r"(a[mt][1]), "=r"(a[mt][2]), "=r"(a[mt][3])
                         : "r"(addr));
        }
        uint32_t bf[8][2];
        #pragma unroll
        for (int p = 0; p < 4; p++) {
            uint32_t addr = bAddrBase +
                ((nbase + p * 16 + bRowSel) * ASTRIDE + kbase + bK8) * 2;
            asm volatile("ldmatrix.sync.aligned.m8n8.x4.shared.b16 {%0,%1,%2,%3}, [%4];"
                         : "=r"(bf[2 * p][0]), "=r"(bf[2 * p][1]),
                           "=r"(bf[2 * p + 1][0]), "=r"(bf[2 * p + 1][1])
                         : "r"(addr));
        }
        #pragma unroll
        for (int mt = 0; mt < 2; mt++)
            #pragma unroll
            for (int nt = 0; nt < 8; nt++)
                asm volatile(
                    "mma.sync.aligned.m16n8k16.row.col.f32.f16.f16.f32 "
                    "{%0,%1,%2,%3}, {%4,%5,%6,%7}, {%8,%9}, {%0,%1,%2,%3};"
                    : "+f"(c[mt][nt][0]), "+f"(c[mt][nt][1]),
                      "+f"(c[mt][nt][2]), "+f"(c[mt][nt][3])
                    : "r"(a[mt][0]), "r"(a[mt][1]), "r"(a[mt][2]), "r"(a[mt][3]),
                      "r"(bf[nt][0]), "r"(bf[nt][1]));
    }

    // epilogue: direct STG with sumw*bias
    #pragma unroll
    for (int mt = 0; mt < 2; mt++) {
        int r0 = mbase + mt * 16 + (lane >> 2);
        int node0 = t * 128 + r0;
        int node1 = node0 + 8;
        float s0 = (node0 < NN) ? g_sumw[node0] : 0.f;
        float s1 = (node1 < NN) ? g_sumw[node1] : 0.f;
        #pragma unroll
        for (int nt = 0; nt < 8; nt++) {
            int col = nbase + nt * 8 + (lane & 3) * 2;
            float2 bb = *(const float2*)(bvec + col);
            if (node0 < NN) {
                float2 v = { c[mt][nt][0] + s0 * bb.x, c[mt][nt][1] + s0 * bb.y };
                *(float2*)(out + (size_t)node0 * 128 + col) = v;
            }
            if (node1 < NN) {
                float2 v = { c[mt][nt][2] + s1 * bb.x, c[mt][nt][3] + s1 * bb.y };
                *(float2*)(out + (size_t)node1 * 128 + col) = v;
            }
        }
    }
}

// ---------------- launch ----------------
extern "C" void kernel_launch(void* const* d_in, const int* in_sizes, int n_in,
                              void* d_out, int out_size) {
    const float* h = nullptr;
    const float* W = nullptr;
    const float* b = nullptr;
    const int*   ed = nullptr;
    for (int i = 0; i < n_in; i++) {
        switch (in_sizes[i]) {
            case NN * 128:  h  = (const float*)d_in[i]; break;      // 6400000
            case 128 * 128: W  = (const float*)d_in[i]; break;      // 16384
            case 128:       b  = (const float*)d_in[i]; break;      // 128
            case 2 * NE:    ed = (const int*)d_in[i]; break;        // 1600000 int32
        }
    }
    float* out = (float*)d_out;

    cudaFuncSetAttribute(k_mm, cudaFuncAttributeMaxDynamicSharedMemorySize, SM_BYTES);

    k_fill   <<<3125, 256>>>(ed, W);
    k_conv   <<<1563, 256>>>(h);
    k_gather <<<6250, 256>>>();
    k_mm     <<<TILES, 256, SM_BYTES>>>(b, out);
}